// round 11
// baseline (speedup 1.0000x reference)
// QuantizedLinear: out = scale * (x @ qw^T) + bias_scale * q_bias
// M=8192, K=4096, N=16384, fp32 in/out, int32 (int8-valued) weights.
//
// sm_103 BASELINE toolchain: tcgen05 rejected by ptxas. Single fp16 HMMA pass
// (weights int8-valued -> exact in fp16; x->fp16 gives norm rel-err ~2e-4).
// R8 measured ~87% of legacy-HMMA ceiling. R9: swizzled CTA rasterization
// (8-m-tile supertile bands) so each wave's B working set fits L2 ->
// shorter cp.async tails -> close the issue gap.
#include <cuda_runtime.h>
#include <cuda_fp16.h>
#include <cstdint>

// ---------------- problem constants ----------------
constexpr int Mdim = 8192;
constexpr int Ndim = 16384;
constexpr int Kdim = 4096;

constexpr int BM = 128;
constexpr int BN = 128;
constexpr int BK = 64;              // 64 fp16 = 128B = one swizzle row
constexpr int STAGES = 3;
constexpr int NKT = Kdim / BK;      // 64 k-iterations

// SMEM layout (dynamic)
constexpr int OFF_BIAS  = 0;        // 128 floats
constexpr int OFF_STAGE = 1024;
constexpr int STAGE_STRIDE = 32768; // A 16K | B 16K
constexpr int A_OFF = 0;
constexpr int B_OFF = 16384;
constexpr int SMEM_TOTAL = OFF_STAGE + STAGES * STAGE_STRIDE; // 99328

// ---------------- device scratch (no cudaMalloc allowed) ----------------
__device__ uint4 g_wh[(size_t)Ndim * Kdim * 2 / 16]; // 128MB fp16 weights
__device__ uint4 g_xh[(size_t)Mdim * Kdim * 2 / 16]; //  64MB fp16 x

// ---------------- helpers ----------------
__device__ __forceinline__ uint32_t smem_u32(const void* p) {
    uint32_t a;
    asm("{ .reg .u64 t; cvta.to.shared.u64 t, %1; cvt.u32.u64 %0, t; }" : "=r"(a) : "l"(p));
    return a;
}
// 128B-row swizzle: XOR 16B-chunk index with (row & 7)
__device__ __forceinline__ uint32_t swz(uint32_t byte_off) {
    return byte_off ^ ((byte_off >> 3) & 0x70);
}
__device__ __forceinline__ void cp16(uint32_t dst, const void* src) {
    asm volatile("cp.async.cg.shared.global [%0], [%1], 16;" :: "r"(dst), "l"(src) : "memory");
}
__device__ __forceinline__ void cp_commit() {
    asm volatile("cp.async.commit_group;" ::: "memory");
}
__device__ __forceinline__ void cp_wait1() {
    asm volatile("cp.async.wait_group 1;" ::: "memory");
}
__device__ __forceinline__ void ldsm_x4(uint32_t r[4], uint32_t addr) {
    asm volatile("ldmatrix.sync.aligned.m8n8.x4.shared.b16 {%0,%1,%2,%3}, [%4];"
                 : "=r"(r[0]), "=r"(r[1]), "=r"(r[2]), "=r"(r[3]) : "r"(addr));
}
__device__ __forceinline__ void mma16816(float c[4], const uint32_t a[4], const uint32_t b[2]) {
    asm volatile(
        "mma.sync.aligned.m16n8k16.row.col.f32.f16.f16.f32 "
        "{%0,%1,%2,%3}, {%4,%5,%6,%7}, {%8,%9}, {%0,%1,%2,%3};"
        : "+f"(c[0]), "+f"(c[1]), "+f"(c[2]), "+f"(c[3])
        : "r"(a[0]), "r"(a[1]), "r"(a[2]), "r"(a[3]), "r"(b[0]), "r"(b[1]));
}

// ---------------- preconvert kernels ----------------
__global__ void convert_w_kernel(const int* __restrict__ qw) {
    __half2* wh2 = reinterpret_cast<__half2*>(g_wh);
    const int4* qw4 = reinterpret_cast<const int4*>(qw);
    const size_t n4 = (size_t)Ndim * Kdim / 4;
    const size_t stride = (size_t)gridDim.x * blockDim.x;
    for (size_t i = (size_t)blockIdx.x * blockDim.x + threadIdx.x; i < n4; i += stride) {
        int4 v = qw4[i];
        __half2 a, b;
        a.x = __float2half_rn((float)v.x);
        a.y = __float2half_rn((float)v.y);
        b.x = __float2half_rn((float)v.z);
        b.y = __float2half_rn((float)v.w);
        wh2[i * 2]     = a;
        wh2[i * 2 + 1] = b;
    }
}

__global__ void convert_x_kernel(const float* __restrict__ x) {
    __half2* xh2 = reinterpret_cast<__half2*>(g_xh);
    const float4* x4 = reinterpret_cast<const float4*>(x);
    const size_t n4 = (size_t)Mdim * Kdim / 4;
    const size_t stride = (size_t)gridDim.x * blockDim.x;
    for (size_t i = (size_t)blockIdx.x * blockDim.x + threadIdx.x; i < n4; i += stride) {
        float4 v = x4[i];
        __half2 a, b;
        a.x = __float2half_rn(v.x);
        a.y = __float2half_rn(v.y);
        b.x = __float2half_rn(v.z);
        b.y = __float2half_rn(v.w);
        xh2[i * 2]     = a;
        xh2[i * 2 + 1] = b;
    }
}

// ---------------- main GEMM kernel ----------------
__global__ void __launch_bounds__(256, 2)
gemm_kernel(const int* __restrict__ qbias,
            const float* __restrict__ scale_p,
            const float* __restrict__ bscale_p,
            float* __restrict__ out) {
    extern __shared__ char smem[];
    const uint32_t sbase = smem_u32(smem);
    const int tid  = threadIdx.x;
    const int wid  = tid >> 5;
    const int lane = tid & 31;
    const int wm = wid >> 2;   // 0..1  -> 64-row M slab
    const int wn = wid & 3;    // 0..3  -> 32-col N slab

    const __half* xh = reinterpret_cast<const __half*>(g_xh);
    const __half* wh = reinterpret_cast<const __half*>(g_wh);

    // -------- swizzled rasterization: supertile = 8 m-tiles tall --------
    // bands of G m-tiles; within a band, n advances slowly so a wave's
    // working set (~8 A tiles + ~37 B tiles ~ 45MB) fits in L2.
    constexpr int NUM_N = Ndim / BN;  // 128
    constexpr int G = 8;              // m-tiles per band (64 % 8 == 0)
    const int bid  = blockIdx.y * NUM_N + blockIdx.x;
    const int band = bid / (G * NUM_N);
    const int rr   = bid % (G * NUM_N);
    const int m_idx = band * G + (rr % G);
    const int n_idx = rr / G;
    const int n0 = n_idx * BN;
    const int m0 = m_idx * BM;

    // bias staging: biasS[j] = bias_scale * q_bias[n0 + j]
    {
        float bsc = bscale_p[0];
        float* sb = reinterpret_cast<float*>(smem + OFF_BIAS);
        for (int i = tid; i < BN; i += 256)
            sb[i] = bsc * (float)qbias[n0 + i];
    }

    // -------- per-thread producer address precompute --------
    // Each tile = 128 rows x 8 chunks of 16B = 1024 chunks; 256 threads x 4.
    const __half* pA[4];
    const __half* pB[4];
    uint32_t dA[4];
    #pragma unroll
    for (int i = 0; i < 4; i++) {
        int q = i * 256 + tid;
        int row = q >> 3, ch = q & 7;
        dA[i] = swz((uint32_t)(row * 128 + ch * 16));
        pA[i] = xh + (size_t)(m0 + row) * Kdim + ch * 8;
        pB[i] = wh + (size_t)(n0 + row) * Kdim + ch * 8;
    }

    // -------- accumulators --------
    float acc[4][4][4];
    #pragma unroll
    for (int mi = 0; mi < 4; mi++)
        #pragma unroll
        for (int ni = 0; ni < 4; ni++)
            #pragma unroll
            for (int j = 0; j < 4; j++)
                acc[mi][ni][j] = 0.0f;

    // -------- prologue: prefetch stages 0..STAGES-2 --------
    #pragma unroll
    for (int s = 0; s < STAGES - 1; s++) {
        const uint32_t sb_ = sbase + OFF_STAGE + s * STAGE_STRIDE;
        const int k0 = s * BK;
        #pragma unroll
        for (int i = 0; i < 4; i++) {
            cp16(sb_ + A_OFF + dA[i], pA[i] + k0);
            cp16(sb_ + B_OFF + dA[i], pB[i] + k0);
        }
        cp_commit();
    }

    // -------- mainloop --------
    const int mrow_base = wm * 64;
    const int nb_base   = wn * 32;

    // ldmatrix lane-invariant pieces (verified mapping)
    const int a_row_in  = lane & 15;
    const int a_ksel    = lane >> 4;
    const int b_nrow_in = ((lane >> 4) << 3) + (lane & 7);
    const int b_ksel    = (lane >> 3) & 1;

    int st = 0;
    for (int kt = 0; kt < NKT; kt++) {
        cp_wait1();
        __syncthreads();

        // issue loads for kt+STAGES-1 into the stage freed last iteration
        {
            int kt_next = kt + STAGES - 1;
            if (kt_next < NKT) {
                int stn = st + (STAGES - 1); if (stn >= STAGES) stn -= STAGES;
                const uint32_t sb_ = sbase + OFF_STAGE + stn * STAGE_STRIDE;
                const int k0 = kt_next * BK;
                #pragma unroll
                for (int i = 0; i < 4; i++) {
                    cp16(sb_ + A_OFF + dA[i], pA[i] + k0);
                    cp16(sb_ + B_OFF + dA[i], pB[i] + k0);
                }
            }
            cp_commit(); // commit (possibly empty) to keep wait counts aligned
        }

        // consume stage st
        const uint32_t sA = sbase + OFF_STAGE + st * STAGE_STRIDE + A_OFF;
        const uint32_t sB = sbase + OFF_STAGE + st * STAGE_STRIDE + B_OFF;

        #pragma unroll
        for (int s = 0; s < 4; s++) {          // 4 k-steps of 16
            // ---- B fragments: 4 n-chunks of 8 ----
            uint32_t bfr[4][2];
            {
                uint32_t t[4];
                int nrow = nb_base + b_nrow_in;
                int ch = 2 * s + b_ksel;
                ldsm_x4(t, sB + (uint32_t)nrow * 128 + (uint32_t)((ch ^ (nrow & 7)) << 4));
                bfr[0][0] = t[0]; bfr[0][1] = t[1];
                bfr[1][0] = t[2]; bfr[1][1] = t[3];
                nrow += 16;
                ldsm_x4(t, sB + (uint32_t)nrow * 128 + (uint32_t)((ch ^ (nrow & 7)) << 4));
                bfr[2][0] = t[0]; bfr[2][1] = t[1];
                bfr[3][0] = t[2]; bfr[3][1] = t[3];
            }
            // ---- A, 4 m-chunks of 16 ----
            #pragma unroll
            for (int mi = 0; mi < 4; mi++) {
                int arow = mrow_base + mi * 16 + a_row_in;
                int ch = 2 * s + a_ksel;
                uint32_t off = (uint32_t)arow * 128 + (uint32_t)((ch ^ (arow & 7)) << 4);
                uint32_t af[4];
                ldsm_x4(af, sA + off);
                #pragma unroll
                for (int ni = 0; ni < 4; ni++)
                    mma16816(acc[mi][ni], af, bfr[ni]);
            }
        }

        st = (st + 1 == STAGES) ? 0 : st + 1;
    }

    // -------- epilogue: out = scale*acc + biasS --------
    const float sc = scale_p[0];
    const float* bs = reinterpret_cast<const float*>(smem + OFF_BIAS);
    const int gr = lane >> 2;
    const int gc = (lane & 3) * 2;
    #pragma unroll
    for (int mi = 0; mi < 4; mi++) {
        const int r = m0 + wm * 64 + mi * 16 + gr;
        #pragma unroll
        for (int ni = 0; ni < 4; ni++) {
            const int cl = wn * 32 + ni * 8 + gc;   // local col in [0,128)
            const int c  = n0 + cl;
            float2 v;
            v.x = fmaf(sc, acc[mi][ni][0], bs[cl]);
            v.y = fmaf(sc, acc[mi][ni][1], bs[cl + 1]);
            *reinterpret_cast<float2*>(out + (size_t)r * Ndim + c) = v;
            v.x = fmaf(sc, acc[mi][ni][2], bs[cl]);
            v.y = fmaf(sc, acc[mi][ni][3], bs[cl + 1]);
            *reinterpret_cast<float2*>(out + (size_t)(r + 8) * Ndim + c) = v;
        }
    }
}

// ---------------- launch ----------------
extern "C" void kernel_launch(void* const* d_in, const int* in_sizes, int n_in,
                              void* d_out, int out_size) {
    const float* x   = (const float*)d_in[0];
    const int*   qw  = (const int*)d_in[1];
    const int*   qb  = (const int*)d_in[2];
    const float* sc  = (const float*)d_in[3];
    const float* bsc = (const float*)d_in[4];
    float* out = (float*)d_out;

    convert_w_kernel<<<1184, 256>>>(qw);
    convert_x_kernel<<<1184, 256>>>(x);

    cudaFuncSetAttribute(gemm_kernel, cudaFuncAttributeMaxDynamicSharedMemorySize, SMEM_TOTAL);
    dim3 grid(Ndim / BN, Mdim / BM); // (128, 64) -> swizzled inside kernel
    gemm_kernel<<<grid, 256, SMEM_TOTAL>>>(qb, sc, bsc, out);
}

// round 12
// speedup vs baseline: 1.0340x; 1.0340x over previous
// QuantizedLinear: out = scale * (x @ qw^T) + bias_scale * q_bias
// M=8192, K=4096, N=16384, fp32 in/out, int32 (int8-valued) weights.
//
// sm_103 BASELINE toolchain: tcgen05 rejected by ptxas. Single fp16 HMMA pass
// (weights int8-valued -> exact in fp16; x->fp16 -> norm rel-err ~2e-4).
// R12: replace wait_group+__syncthreads lockstep with per-stage mbarriers
// (full: 256 cp-arrives; empty: 8 warp-arrives). Warps run decoupled with
// 1-iter skew tolerance -> no BAR.SYNC drain per k-iter. 2 CTAs/SM kept.
#include <cuda_runtime.h>
#include <cuda_fp16.h>
#include <cstdint>

// ---------------- problem constants ----------------
constexpr int Mdim = 8192;
constexpr int Ndim = 16384;
constexpr int Kdim = 4096;

constexpr int BM = 128;
constexpr int BN = 128;
constexpr int BK = 64;              // 64 fp16 = 128B = one swizzle row
constexpr int STAGES = 3;
constexpr int NKT = Kdim / BK;      // 64 k-iterations

// SMEM layout (dynamic)
constexpr int OFF_FULL  = 0;        // 3 x 8B mbarriers
constexpr int OFF_EMPTY = 32;       // 3 x 8B mbarriers
constexpr int OFF_BIAS  = 128;      // 128 floats
constexpr int OFF_STAGE = 1024;
constexpr int STAGE_STRIDE = 32768; // A 16K | B 16K
constexpr int A_OFF = 0;
constexpr int B_OFF = 16384;
constexpr int SMEM_TOTAL = OFF_STAGE + STAGES * STAGE_STRIDE; // 99328

// ---------------- device scratch (no cudaMalloc allowed) ----------------
__device__ uint4 g_wh[(size_t)Ndim * Kdim * 2 / 16]; // 128MB fp16 weights
__device__ uint4 g_xh[(size_t)Mdim * Kdim * 2 / 16]; //  64MB fp16 x

// ---------------- helpers ----------------
__device__ __forceinline__ uint32_t smem_u32(const void* p) {
    uint32_t a;
    asm("{ .reg .u64 t; cvta.to.shared.u64 t, %1; cvt.u32.u64 %0, t; }" : "=r"(a) : "l"(p));
    return a;
}
// 128B-row swizzle: XOR 16B-chunk index with (row & 7)
__device__ __forceinline__ uint32_t swz(uint32_t byte_off) {
    return byte_off ^ ((byte_off >> 3) & 0x70);
}
__device__ __forceinline__ void cp16(uint32_t dst, const void* src) {
    asm volatile("cp.async.cg.shared.global [%0], [%1], 16;" :: "r"(dst), "l"(src) : "memory");
}
__device__ __forceinline__ void cp_arrive(uint32_t mbar) {
    asm volatile("cp.async.mbarrier.arrive.noinc.shared::cta.b64 [%0];" :: "r"(mbar) : "memory");
}
#define MBARRIER_INIT(addr, count) \
    asm volatile("mbarrier.init.shared.b64 [%0], %1;" :: "r"((uint32_t)(addr)), "r"((uint32_t)(count)) : "memory")
#define MBARRIER_ARRIVE(addr) \
    asm volatile("mbarrier.arrive.shared.b64 _, [%0];" :: "r"((uint32_t)(addr)) : "memory")

#define MBARRIER_WAIT_PARITY(mbar_smem_addr, phase_parity) do { \
    uint32_t _mbar = (uint32_t)(mbar_smem_addr); \
    uint32_t _parity = (uint32_t)(phase_parity); \
    uint32_t _done; \
    asm volatile( \
        "{\n\t" \
        ".reg .pred p;\n\t" \
        "mbarrier.try_wait.parity.acquire.cta.shared::cta.b64 p, [%1], %2;\n\t" \
        "selp.b32 %0, 1, 0, p;\n\t" \
        "}" \
        : "=r"(_done) : "r"(_mbar), "r"(_parity) : "memory"); \
    if (!_done) { \
        asm volatile( \
            "{\n\t" \
            ".reg .pred P1;\n\t" \
            "WAIT_LOOP_%=:\n\t" \
            "mbarrier.try_wait.parity.acquire.cta.shared::cta.b64 P1, [%0], %1, 0x989680;\n\t" \
            "@P1 bra.uni WAIT_DONE_%=;\n\t" \
            "bra.uni WAIT_LOOP_%=;\n\t" \
            "WAIT_DONE_%=:\n\t" \
            "}" \
            :: "r"(_mbar), "r"(_parity) : "memory"); \
    } \
} while(0)

__device__ __forceinline__ void ldsm_x4(uint32_t r[4], uint32_t addr) {
    asm volatile("ldmatrix.sync.aligned.m8n8.x4.shared.b16 {%0,%1,%2,%3}, [%4];"
                 : "=r"(r[0]), "=r"(r[1]), "=r"(r[2]), "=r"(r[3]) : "r"(addr));
}
__device__ __forceinline__ void mma16816(float c[4], const uint32_t a[4], const uint32_t b[2]) {
    asm volatile(
        "mma.sync.aligned.m16n8k16.row.col.f32.f16.f16.f32 "
        "{%0,%1,%2,%3}, {%4,%5,%6,%7}, {%8,%9}, {%0,%1,%2,%3};"
        : "+f"(c[0]), "+f"(c[1]), "+f"(c[2]), "+f"(c[3])
        : "r"(a[0]), "r"(a[1]), "r"(a[2]), "r"(a[3]), "r"(b[0]), "r"(b[1]));
}

// ---------------- preconvert kernels ----------------
__global__ void convert_w_kernel(const int* __restrict__ qw) {
    __half2* wh2 = reinterpret_cast<__half2*>(g_wh);
    const int4* qw4 = reinterpret_cast<const int4*>(qw);
    const size_t n4 = (size_t)Ndim * Kdim / 4;
    const size_t stride = (size_t)gridDim.x * blockDim.x;
    for (size_t i = (size_t)blockIdx.x * blockDim.x + threadIdx.x; i < n4; i += stride) {
        int4 v = qw4[i];
        __half2 a, b;
        a.x = __float2half_rn((float)v.x);
        a.y = __float2half_rn((float)v.y);
        b.x = __float2half_rn((float)v.z);
        b.y = __float2half_rn((float)v.w);
        wh2[i * 2]     = a;
        wh2[i * 2 + 1] = b;
    }
}

__global__ void convert_x_kernel(const float* __restrict__ x) {
    __half2* xh2 = reinterpret_cast<__half2*>(g_xh);
    const float4* x4 = reinterpret_cast<const float4*>(x);
    const size_t n4 = (size_t)Mdim * Kdim / 4;
    const size_t stride = (size_t)gridDim.x * blockDim.x;
    for (size_t i = (size_t)blockIdx.x * blockDim.x + threadIdx.x; i < n4; i += stride) {
        float4 v = x4[i];
        __half2 a, b;
        a.x = __float2half_rn(v.x);
        a.y = __float2half_rn(v.y);
        b.x = __float2half_rn(v.z);
        b.y = __float2half_rn(v.w);
        xh2[i * 2]     = a;
        xh2[i * 2 + 1] = b;
    }
}

// ---------------- main GEMM kernel ----------------
__global__ void __launch_bounds__(256, 2)
gemm_kernel(const int* __restrict__ qbias,
            const float* __restrict__ scale_p,
            const float* __restrict__ bscale_p,
            float* __restrict__ out) {
    extern __shared__ char smem[];
    const uint32_t sbase = smem_u32(smem);
    const int tid  = threadIdx.x;
    const int wid  = tid >> 5;
    const int lane = tid & 31;
    const int wm = wid >> 2;   // 0..1  -> 64-row M slab
    const int wn = wid & 3;    // 0..3  -> 32-col N slab

    const __half* xh = reinterpret_cast<const __half*>(g_xh);
    const __half* wh = reinterpret_cast<const __half*>(g_wh);

    // -------- swizzled rasterization: supertile = 8 m-tiles tall --------
    constexpr int NUM_N = Ndim / BN;  // 128
    constexpr int G = 8;              // m-tiles per band
    const int bid  = blockIdx.y * NUM_N + blockIdx.x;
    const int band = bid / (G * NUM_N);
    const int rr   = bid % (G * NUM_N);
    const int m_idx = band * G + (rr % G);
    const int n_idx = rr / G;
    const int n0 = n_idx * BN;
    const int m0 = m_idx * BM;

    // -------- barriers + bias staging (prologue-only __syncthreads) --------
    if (tid == 0) {
        #pragma unroll
        for (int s = 0; s < STAGES; s++) {
            MBARRIER_INIT(sbase + OFF_FULL  + s * 8, 256); // 256 cp-arrive threads
            MBARRIER_INIT(sbase + OFF_EMPTY + s * 8, 8);   // 8 warp arrives
        }
    }
    {
        float bsc = bscale_p[0];
        float* sb = reinterpret_cast<float*>(smem + OFF_BIAS);
        for (int i = tid; i < BN; i += 256)
            sb[i] = bsc * (float)qbias[n0 + i];
    }
    __syncthreads();

    // -------- per-thread producer address precompute --------
    const __half* pA[4];
    const __half* pB[4];
    uint32_t dA[4];
    #pragma unroll
    for (int i = 0; i < 4; i++) {
        int q = i * 256 + tid;
        int row = q >> 3, ch = q & 7;
        dA[i] = swz((uint32_t)(row * 128 + ch * 16));
        pA[i] = xh + (size_t)(m0 + row) * Kdim + ch * 8;
        pB[i] = wh + (size_t)(n0 + row) * Kdim + ch * 8;
    }

    // -------- accumulators --------
    float acc[4][4][4];
    #pragma unroll
    for (int mi = 0; mi < 4; mi++)
        #pragma unroll
        for (int ni = 0; ni < 4; ni++)
            #pragma unroll
            for (int j = 0; j < 4; j++)
                acc[mi][ni][j] = 0.0f;

    // -------- prologue: fill stages 0..STAGES-2 (kt = 0,1) --------
    #pragma unroll
    for (int s = 0; s < STAGES - 1; s++) {
        const uint32_t sb_ = sbase + OFF_STAGE + s * STAGE_STRIDE;
        const int k0 = s * BK;
        #pragma unroll
        for (int i = 0; i < 4; i++) {
            cp16(sb_ + A_OFF + dA[i], pA[i] + k0);
            cp16(sb_ + B_OFF + dA[i], pB[i] + k0);
        }
        cp_arrive(sbase + OFF_FULL + s * 8);
    }

    // -------- mainloop: decoupled producer/consumer cursors per warp --------
    const int mrow_base = wm * 64;
    const int nb_base   = wn * 32;
    const int a_row_in  = lane & 15;
    const int a_ksel    = lane >> 4;
    const int b_nrow_in = ((lane >> 4) << 3) + (lane & 7);
    const int b_ksel    = (lane >> 3) & 1;

    int pst = STAGES - 1, pph = 1;   // producer: next fill is stage 2, virgin phase
    int cst = 0,          cph = 0;   // consumer

    for (int kt = 0; kt < NKT; kt++) {
        // ---- produce kt+2 into pst (freed by all warps after kt-1) ----
        {
            int ktp = kt + (STAGES - 1);
            if (ktp < NKT) {
                MBARRIER_WAIT_PARITY(sbase + OFF_EMPTY + pst * 8, pph);
                const uint32_t sb_ = sbase + OFF_STAGE + pst * STAGE_STRIDE;
                const int k0 = ktp * BK;
                #pragma unroll
                for (int i = 0; i < 4; i++) {
                    cp16(sb_ + A_OFF + dA[i], pA[i] + k0);
                    cp16(sb_ + B_OFF + dA[i], pB[i] + k0);
                }
                cp_arrive(sbase + OFF_FULL + pst * 8);
            }
            if (++pst == STAGES) { pst = 0; pph ^= 1; }
        }

        // ---- consume kt from cst ----
        MBARRIER_WAIT_PARITY(sbase + OFF_FULL + cst * 8, cph);
        const uint32_t sA = sbase + OFF_STAGE + cst * STAGE_STRIDE + A_OFF;
        const uint32_t sB = sbase + OFF_STAGE + cst * STAGE_STRIDE + B_OFF;

        #pragma unroll
        for (int s = 0; s < 4; s++) {          // 4 k-steps of 16
            uint32_t bfr[4][2];
            {
                uint32_t t[4];
                int nrow = nb_base + b_nrow_in;
                int ch = 2 * s + b_ksel;
                ldsm_x4(t, sB + (uint32_t)nrow * 128 + (uint32_t)((ch ^ (nrow & 7)) << 4));
                bfr[0][0] = t[0]; bfr[0][1] = t[1];
                bfr[1][0] = t[2]; bfr[1][1] = t[3];
                nrow += 16;
                ldsm_x4(t, sB + (uint32_t)nrow * 128 + (uint32_t)((ch ^ (nrow & 7)) << 4));
                bfr[2][0] = t[0]; bfr[2][1] = t[1];
                bfr[3][0] = t[2]; bfr[3][1] = t[3];
            }
            #pragma unroll
            for (int mi = 0; mi < 4; mi++) {
                int arow = mrow_base + mi * 16 + a_row_in;
                int ch = 2 * s + a_ksel;
                uint32_t off = (uint32_t)arow * 128 + (uint32_t)((ch ^ (arow & 7)) << 4);
                uint32_t af[4];
                ldsm_x4(af, sA + off);
                #pragma unroll
                for (int ni = 0; ni < 4; ni++)
                    mma16816(acc[mi][ni], af, bfr[ni]);
            }
        }

        // release the stage: whole warp done reading, one arrive per warp
        __syncwarp();
        if (lane == 0) MBARRIER_ARRIVE(sbase + OFF_EMPTY + cst * 8);
        if (++cst == STAGES) { cst = 0; cph ^= 1; }
    }

    // -------- epilogue: out = scale*acc + biasS --------
    const float sc = scale_p[0];
    const float* bs = reinterpret_cast<const float*>(smem + OFF_BIAS);
    const int gr = lane >> 2;
    const int gc = (lane & 3) * 2;
    #pragma unroll
    for (int mi = 0; mi < 4; mi++) {
        const int r = m0 + wm * 64 + mi * 16 + gr;
        #pragma unroll
        for (int ni = 0; ni < 4; ni++) {
            const int cl = wn * 32 + ni * 8 + gc;   // local col in [0,128)
            const int c  = n0 + cl;
            float2 v;
            v.x = fmaf(sc, acc[mi][ni][0], bs[cl]);
            v.y = fmaf(sc, acc[mi][ni][1], bs[cl + 1]);
            *reinterpret_cast<float2*>(out + (size_t)r * Ndim + c) = v;
            v.x = fmaf(sc, acc[mi][ni][2], bs[cl]);
            v.y = fmaf(sc, acc[mi][ni][3], bs[cl + 1]);
            *reinterpret_cast<float2*>(out + (size_t)(r + 8) * Ndim + c) = v;
        }
    }
}

// ---------------- launch ----------------
extern "C" void kernel_launch(void* const* d_in, const int* in_sizes, int n_in,
                              void* d_out, int out_size) {
    const float* x   = (const float*)d_in[0];
    const int*   qw  = (const int*)d_in[1];
    const int*   qb  = (const int*)d_in[2];
    const float* sc  = (const float*)d_in[3];
    const float* bsc = (const float*)d_in[4];
    float* out = (float*)d_out;

    convert_w_kernel<<<1184, 256>>>(qw);
    convert_x_kernel<<<1184, 256>>>(x);

    cudaFuncSetAttribute(gemm_kernel, cudaFuncAttributeMaxDynamicSharedMemorySize, SMEM_TOTAL);
    dim3 grid(Ndim / BN, Mdim / BM); // (128, 64) -> swizzled inside kernel
    gemm_kernel<<<grid, 256, SMEM_TOTAL>>>(qb, sc, bsc, out);
}